// round 4
// baseline (speedup 1.0000x reference)
#include <cuda_runtime.h>
#include <cuda_bf16.h>
#include <math.h>

#define BB 8
#define NN (512*512)
#define DD 32
#define KK 64
#define PUSH_MARGIN 0.25f

#define BLOCKS_PER_BATCH 64
#define THREADS1 128
#define WARPS1 4
#define PPB (NN / BLOCKS_PER_BATCH)   // 4096
#define PPW (PPB / WARPS1)            // 1024
#define GRP 16                        // points per prefetch buffer (4 x LDG.128)

// Scratch (device globals: no allocation allowed)
__device__ float g_sums[BB * KK * DD];
__device__ float g_cntp[BB][4][KK];   // per-chunk count partials (no zeroing needed)

// ---------------------------------------------------------------------------
// Kernel A: label histogram (per-(warp,lane) copies: zero atomics) + zero g_sums
// grid = BB*4 blocks x 128 threads; block (b, ch) handles NN/4 labels.
// ---------------------------------------------------------------------------
__global__ __launch_bounds__(128)
void hist_kernel(const int* __restrict__ lab) {
    __shared__ int h[4][KK][32];          // 32 KB, copy index = (warp, lane)
    const int tid  = threadIdx.x;
    const int w    = tid >> 5;
    const int lane = tid & 31;
    const int blk  = blockIdx.x;
    const int b    = blk >> 2;
    const int ch   = blk & 3;

    for (int i = tid; i < 4 * KK * 32; i += 128)
        ((int*)h)[i] = 0;
    __syncthreads();

    const int4* __restrict__ lab4 =
        (const int4*)(lab + (size_t)b * NN + (size_t)ch * (NN / 4));
    int* __restrict__ hw = &h[w][0][0];

    // NN/4 labels = 16384 int4; 128 threads -> 128 int4 each
#pragma unroll 4
    for (int i = 0; i < 128; i++) {
        int4 L = lab4[i * 128 + tid];
        hw[L.x * 32 + lane]++;     // addr includes lane: race-free, bank==lane
        hw[L.y * 32 + lane]++;
        hw[L.z * 32 + lane]++;
        hw[L.w * 32 + lane]++;
    }
    __syncthreads();

    if (tid < KK) {
        int s = 0;
#pragma unroll
        for (int ww = 0; ww < 4; ww++)
            for (int l = 0; l < 32; l++)
                s += h[ww][tid][l];
        g_cntp[b][ch][tid] = (float)s;
    }

    // zero g_sums: 16384 floats / 32 blocks = 512 per block
    for (int i = tid; i < 512; i += 128)
        g_sums[blk * 512 + i] = 0.0f;
}

// ---------------------------------------------------------------------------
// Kernel B: segment sum, fully vectorized float4 path.
// Lane roles: j = lane>>3 (point in quad), c = lane&7 (float4 chunk of D=32).
// One LDG.128 loads 4 points; one LDS.128/STS.128 updates 4 points' rows
// (phase = 8 lanes = one point's 128B row: conflict-free).
// Duplicate labels within a quad (would race inside one STS.128) are detected
// per 16-point group via match_any+ballot and handled by a serialized path.
// ---------------------------------------------------------------------------
__global__ __launch_bounds__(THREADS1)
void seg_reduce_kernel(const float* __restrict__ emb, const int* __restrict__ lab) {
    __shared__ float sacc[WARPS1][KK * DD];   // 32 KB

    const int tid  = threadIdx.x;
    const int w    = tid >> 5;
    const int lane = tid & 31;
    const int b    = blockIdx.y;
    const int j4   = lane >> 3;
    const int c8   = lane & 7;
    const unsigned FULL = 0xffffffffu;

    for (int i = tid; i < WARPS1 * KK * DD; i += THREADS1)
        ((float*)sacc)[i] = 0.0f;
    __syncthreads();

    const int p0   = blockIdx.x * PPB + w * PPW;
    const int pend = p0 + PPW;
    const float4* __restrict__ eb4 =
        (const float4*)(emb + (size_t)b * NN * DD);
    const int* __restrict__ lb = lab + (size_t)b * NN;
    float4* __restrict__ accv = (float4*)(sacc[w]);

    float4 vA[4], vB[4];
    int lA, lB;
    const int lsel = lane & 15;

#define PREFETCH(vv, ll, pp)                                              \
    do {                                                                  \
        ll = lb[(pp) + lsel];                                             \
        _Pragma("unroll")                                                 \
        for (int q = 0; q < 4; q++)                                       \
            vv[q] = eb4[(size_t)((pp) + 4 * q + j4) * 8 + c8];            \
    } while (0)

#define CONSUME(vv, ll)                                                   \
    do {                                                                  \
        int key = (ll) | ((lane >> 2) << 6);                              \
        unsigned peers = __match_any_sync(FULL, key);                     \
        unsigned dupb = __ballot_sync(FULL, __popc(peers) > 1) & 0xFFFFu; \
        _Pragma("unroll")                                                 \
        for (int q = 0; q < 4; q++) {                                     \
            int l = __shfl_sync(FULL, (ll), 4 * q + j4);                  \
            float4 mv = vv[q];                                            \
            int idx = l * 8 + c8;                                         \
            if (((dupb >> (4 * q)) & 0xF) == 0) {                         \
                float4 t = accv[idx];                                     \
                t.x += mv.x; t.y += mv.y; t.z += mv.z; t.w += mv.w;       \
                accv[idx] = t;                                            \
            } else {                                                      \
                _Pragma("unroll")                                         \
                for (int jj = 0; jj < 4; jj++) {                          \
                    if (j4 == jj) {                                       \
                        float4 t = accv[idx];                             \
                        t.x += mv.x; t.y += mv.y;                         \
                        t.z += mv.z; t.w += mv.w;                         \
                        accv[idx] = t;                                    \
                    }                                                     \
                }                                                         \
            }                                                             \
        }                                                                 \
    } while (0)

    PREFETCH(vA, lA, p0);

#pragma unroll 1
    for (int p = p0; p < pend; p += 2 * GRP) {
        PREFETCH(vB, lB, p + GRP);
        CONSUME(vA, lA);
        if (p + 2 * GRP < pend) {
            PREFETCH(vA, lA, p + 2 * GRP);
        }
        CONSUME(vB, lB);
    }
    __syncthreads();

    // Flush: combine 4 warp accumulators, atomicAdd into global scratch
    float* __restrict__ gs = g_sums + b * KK * DD;
    for (int i = tid; i < KK * DD; i += THREADS1) {
        float s = sacc[0][i] + sacc[1][i] + sacc[2][i] + sacc[3][i];
        atomicAdd(&gs[i], s);
    }
#undef PREFETCH
#undef CONSUME
}

// ---------------------------------------------------------------------------
// Kernel C: finalize — single block, all batches, direct store (no pre-zero)
// ---------------------------------------------------------------------------
#define CSTRIDE (DD + 1)

__global__ __launch_bounds__(512)
void finalize_kernel(float* __restrict__ out) {
    const int tid = threadIdx.x;
    __shared__ float cent[KK * CSTRIDE];
    __shared__ float cnts[KK];
    __shared__ float red[512];
    __shared__ float bres[BB];

    for (int b = 0; b < BB; b++) {
        if (tid < KK)
            cnts[tid] = g_cntp[b][0][tid] + g_cntp[b][1][tid] +
                        g_cntp[b][2][tid] + g_cntp[b][3][tid];
        __syncthreads();

        for (int i = tid; i < KK * DD; i += 512) {
            int k = i >> 5, d = i & 31;
            cent[k * CSTRIDE + d] = g_sums[b * KK * DD + i] / fmaxf(cnts[k], 1.0f);
        }
        __syncthreads();

        float local = 0.0f;
        for (int pr = tid; pr < KK * KK; pr += 512) {
            int i = pr >> 6, j = pr & 63;
            if (i < j && cnts[i] > 0.5f && cnts[j] > 0.5f) {
                float ds = 0.0f;
#pragma unroll
                for (int d = 0; d < DD; d++)
                    ds += fabsf(cent[i * CSTRIDE + d] - cent[j * CSTRIDE + d]);
                float h = fmaxf(PUSH_MARGIN - ds, 0.0f);
                local += h * h;
            }
        }
        red[tid] = local;
        __syncthreads();
        for (int s = 256; s > 0; s >>= 1) {
            if (tid < s) red[tid] += red[tid + s];
            __syncthreads();
        }
        if (tid == 0) {
            float n = 0.0f;
            for (int k = 0; k < KK; k++)
                n += (cnts[k] > 0.5f) ? 1.0f : 0.0f;
            bres[b] = red[0] / (n * (n - 1.0f) * 0.5f);
        }
        __syncthreads();
    }
    if (tid == 0) {
        float s = 0.0f;
        for (int b = 0; b < BB; b++) s += bres[b];
        out[0] = s / (float)BB;
    }
}

// ---------------------------------------------------------------------------
// Launch
// ---------------------------------------------------------------------------
extern "C" void kernel_launch(void* const* d_in, const int* in_sizes, int n_in,
                              void* d_out, int out_size) {
    const float* emb = (const float*)d_in[0];
    const int*   lab = (const int*)d_in[1];
    float*       out = (float*)d_out;

    hist_kernel<<<BB * 4, 128>>>(lab);          // counts + zero g_sums

    dim3 grid1(BLOCKS_PER_BATCH, BB);
    seg_reduce_kernel<<<grid1, THREADS1>>>(emb, lab);

    finalize_kernel<<<1, 512>>>(out);
}